// round 12
// baseline (speedup 1.0000x reference)
#include <cuda_runtime.h>
#include <cstdint>

// Problem constants
#define LDIM   128
#define RDIM   2048
#define EDIM   32
#define FDIM   64
#define KTOT   2048
#define BATCH  8

// Tiling: CTA = 128L x 256R x (ECH*64)k, 512 threads, thread tile 8L x 8R
#define KT       16
#define RT       256
#define ECH      2
#define NSTAGE   ((ECH*FDIM)/KT)     // 8
#define NTHREADS 512
#define AROW     132                 // A tile padded row (words)
#define BROW     260                 // B tile padded row (words)
#define ZROW     260                 // zb padded row (words)

// rbf(d,e) = exp(-((d-mu_e)/sigma)^2) = 2^(-(KC*(d-mu_e))^2)
#define KC_CONST   3.2029930899845557f
#define MU_STEP    (12.0f/31.0f)

// dynamic smem layout (floats)
#define SM_A      0
#define SM_B      (2*KT*AROW)                  // 4224
#define SM_ZB     (SM_B + 2*KT*BROW)           // 12544
#define SM_FLOATS (SM_ZB + LDIM*ZROW)          // 45824
#define SMEM_BYTES (SM_FLOATS*4)               // 183296 B

__device__ __forceinline__ unsigned long long dup2(float x) {
    unsigned long long r;
    unsigned int u = __float_as_uint(x);
    asm("mov.b64 %0, {%1, %1};" : "=l"(r) : "r"(u));
    return r;
}
__device__ __forceinline__ void fma2(unsigned long long &acc,
                                     unsigned long long a,
                                     unsigned long long b) {
    asm("fma.rn.f32x2 %0, %1, %2, %0;" : "+l"(acc) : "l"(a), "l"(b));
}
__device__ __forceinline__ void unpack2(unsigned long long v, float &lo, float &hi) {
    unsigned int a, b;
    asm("mov.b64 {%0, %1}, %2;" : "=r"(a), "=r"(b) : "l"(v));
    lo = __uint_as_float(a);
    hi = __uint_as_float(b);
}
__device__ __forceinline__ float ex2a(float x) {
    float r; asm("ex2.approx.ftz.f32 %0, %1;" : "=f"(r) : "f"(x)); return r;
}
__device__ __forceinline__ float sqrta(float x) {
    float r; asm("sqrt.approx.f32 %0, %1;" : "=f"(r) : "f"(x)); return r;
}

__global__ void ff_init_kernel(float* out) {
    if (threadIdx.x < BATCH) out[threadIdx.x] = 0.0f;
}

__global__ void __launch_bounds__(NTHREADS, 1)
ff_main_kernel(const float* __restrict__ ligf,
               const float* __restrict__ recf,
               const float* __restrict__ ligc,
               const float* __restrict__ recc,
               float* __restrict__ out)
{
    extern __shared__ __align__(16) float smem[];
    float* As = smem + SM_A;
    float* Bs = smem + SM_B;
    float* zb = smem + SM_ZB;

    const int tid  = threadIdx.x;
    const int lane = tid & 31;
    const int w    = tid >> 5;          // 0..15; owns l = w*8 .. w*8+7
    const int l0   = w * 8;
    // lane owns r slots: j<4 -> 4*lane+j ; j>=4 -> 128+4*lane+(j-4)

    const int rt = blockIdx.x;          // 0..7
    const int ec = blockIdx.y;          // 0..15
    const int b  = blockIdx.z;          // 0..7

    const int r0    = rt * RT;
    const int e0    = ec * ECH;
    const int kbase = e0 * FDIM;

    const float* Ag = ligf + (size_t)b * LDIM * KTOT + kbase;
    const float* Bg = recf + ((size_t)b * RDIM + r0) * KTOT + kbase;

    // staging assignment (conflict-free STS: 32 consecutive rows per warp)
    const int arow = tid & 127;         // 0..127
    const int acol = (tid >> 7) * 4;    // 0,4,8,12
    const int brow = tid & 255;         // 0..255
    const int bcol = (tid >> 8) * 8;    // 0,8

    // ---- stage coords into smem (reuse A tile area) ----
    {
        float* lc = As;                 // [128][3]
        float* rc = As + 512;           // [256][3]
        for (int i = tid; i < LDIM * 3; i += NTHREADS)
            lc[i] = ligc[(size_t)b * LDIM * 3 + i];
        for (int i = tid; i < RT * 3; i += NTHREADS)
            rc[i] = recc[((size_t)b * RDIM + r0) * 3 + i];
        __syncthreads();

        // issue stage-0 global prefetch first (overlaps sqrt work below)
        float4 pa  = *(const float4*)(Ag + (size_t)arow * KTOT + acol);
        float4 pb0 = *(const float4*)(Bg + (size_t)brow * KTOT + bcol);
        float4 pb1 = *(const float4*)(Bg + (size_t)brow * KTOT + bcol + 4);

        // ---- zb[l][r] = KC * dist(l, r0+r), 64 entries per thread ----
        {
            const int l  = tid & 127;
            const int rq = tid >> 7;            // 0..3 -> r block of 64
            const float lx = lc[l * 3], ly = lc[l * 3 + 1], lz = lc[l * 3 + 2];
            float* zrow = zb + l * ZROW + rq * 64;
            const float* rcp = rc + rq * 64 * 3;
            #pragma unroll 4
            for (int i = 0; i < 64; i++) {
                float dx = lx - rcp[i * 3], dy = ly - rcp[i * 3 + 1],
                      dz = lz - rcp[i * 3 + 2];
                float dd = fmaf(dx, dx, fmaf(dy, dy, dz * dz));
                zrow[i] = KC_CONST * sqrta(dd);
            }
        }
        __syncthreads();

        // store stage 0 (conflict-free STS)
        {
            float va[4] = {pa.x, pa.y, pa.z, pa.w};
            float vb[8] = {pb0.x, pb0.y, pb0.z, pb0.w,
                           pb1.x, pb1.y, pb1.z, pb1.w};
            #pragma unroll
            for (int j = 0; j < 4; j++)
                As[(acol + j) * AROW + arow] = va[j];
            #pragma unroll
            for (int j = 0; j < 8; j++)
                Bs[(bcol + j) * BROW + brow] = vb[j];
        }
    }

    // acc[p][j]: packed {l = l0+2p, l0+2p+1} x r-slot j
    unsigned long long acc[4][8];
    #pragma unroll
    for (int p = 0; p < 4; p++)
        #pragma unroll
        for (int j = 0; j < 8; j++)
            acc[p][j] = 0ULL;

    float u_acc = 0.0f;

    // prefetch stage 1
    float4 pa, pb0, pb1;
    pa  = *(const float4*)(Ag + (size_t)arow * KTOT + KT + acol);
    pb0 = *(const float4*)(Bg + (size_t)brow * KTOT + KT + bcol);
    pb1 = *(const float4*)(Bg + (size_t)brow * KTOT + KT + bcol + 4);

    #pragma unroll 1
    for (int s = 0; s < NSTAGE; s++) {
        const int buf = s & 1;
        float* Asb = As + buf * (KT * AROW);
        float* Bsb = Bs + buf * (KT * BROW);
        __syncthreads();

        // ---- main compute: KT k-steps, 8L x 8R per thread ----
        #pragma unroll 4
        for (int k = 0; k < KT; k++) {
            // A: 4 l-pairs via 2 LDS.128 (same addr warp-wide)
            unsigned long long a2[4];
            {
                const ulonglong2* Ar = (const ulonglong2*)(Asb + k * AROW + l0);
                ulonglong2 t0 = Ar[0];
                ulonglong2 t1 = Ar[1];
                a2[0] = t0.x; a2[1] = t0.y; a2[2] = t1.x; a2[3] = t1.y;
            }
            // B half 0: r = 4*lane + j
            {
                float4 bf = *(const float4*)(Bsb + k * BROW + 4 * lane);
                unsigned long long b2[4];
                b2[0] = dup2(bf.x); b2[1] = dup2(bf.y);
                b2[2] = dup2(bf.z); b2[3] = dup2(bf.w);
                #pragma unroll
                for (int p = 0; p < 4; p++)
                    #pragma unroll
                    for (int j = 0; j < 4; j++)
                        fma2(acc[p][j], a2[p], b2[j]);
            }
            // B half 1: r = 128 + 4*lane + j
            {
                float4 bf = *(const float4*)(Bsb + k * BROW + 128 + 4 * lane);
                unsigned long long b2[4];
                b2[0] = dup2(bf.x); b2[1] = dup2(bf.y);
                b2[2] = dup2(bf.z); b2[3] = dup2(bf.w);
                #pragma unroll
                for (int p = 0; p < 4; p++)
                    #pragma unroll
                    for (int j = 0; j < 4; j++)
                        fma2(acc[p][4 + j], a2[p], b2[j]);
            }
        }

        // ---- store prefetched next tile; fetch the one after ----
        if (s + 1 < NSTAGE) {
            const int nbuf = (s + 1) & 1;
            float* Asn = As + nbuf * (KT * AROW);
            float* Bsn = Bs + nbuf * (KT * BROW);
            float va[4] = {pa.x, pa.y, pa.z, pa.w};
            float vb[8] = {pb0.x, pb0.y, pb0.z, pb0.w,
                           pb1.x, pb1.y, pb1.z, pb1.w};
            #pragma unroll
            for (int j = 0; j < 4; j++)
                Asn[(acol + j) * AROW + arow] = va[j];
            #pragma unroll
            for (int j = 0; j < 8; j++)
                Bsn[(bcol + j) * BROW + brow] = vb[j];
            if (s + 2 < NSTAGE) {
                const int ko = (s + 2) * KT;
                pa  = *(const float4*)(Ag + (size_t)arow * KTOT + ko + acol);
                pb0 = *(const float4*)(Bg + (size_t)brow * KTOT + ko + bcol);
                pb1 = *(const float4*)(Bg + (size_t)brow * KTOT + ko + bcol + 4);
            }
        }

        // ---- epilogue fold at each e boundary (every 4 stages) ----
        if ((s & 3) == 3) {
            const int e = e0 + (s >> 2);
            const float c2 = KC_CONST * MU_STEP * (float)e;
            #pragma unroll
            for (int p = 0; p < 4; p++) {
                const float* z0p = zb + (l0 + 2 * p) * ZROW + 4 * lane;
                const float* z1p = z0p + ZROW;
                #pragma unroll
                for (int g = 0; g < 2; g++) {
                    float4 za = *(const float4*)(z0p + 128 * g);
                    float4 zc = *(const float4*)(z1p + 128 * g);
                    float z0v[4] = {za.x, za.y, za.z, za.w};
                    float z1v[4] = {zc.x, zc.y, zc.z, zc.w};
                    #pragma unroll
                    for (int j = 0; j < 4; j++) {
                        float dot0, dot1;
                        unpack2(acc[p][4 * g + j], dot0, dot1);
                        float q0 = z0v[j] - c2;
                        float q1 = z1v[j] - c2;
                        u_acc = fmaf(ex2a(-q0 * q0), dot0, u_acc);
                        u_acc = fmaf(ex2a(-q1 * q1), dot1, u_acc);
                        acc[p][4 * g + j] = 0ULL;
                    }
                }
            }
        }
    }

    // ---- block reduction + atomic accumulate into U[b] ----
    #pragma unroll
    for (int o = 16; o > 0; o >>= 1)
        u_acc += __shfl_xor_sync(0xffffffffu, u_acc, o);

    __syncthreads();
    float* red = smem;
    if (lane == 0) red[w] = u_acc;
    __syncthreads();
    if (tid == 0) {
        float ssum = 0.0f;
        #pragma unroll
        for (int ww = 0; ww < NTHREADS / 32; ww++) ssum += red[ww];
        atomicAdd(out + b, ssum * 0.01f);   // ENERGY_SCALE
    }
}

extern "C" void kernel_launch(void* const* d_in, const int* in_sizes, int n_in,
                              void* d_out, int out_size) {
    (void)in_sizes; (void)n_in; (void)out_size;
    const float* lig_feat  = (const float*)d_in[0];
    const float* rec_feat  = (const float*)d_in[1];
    const float* lig_coord = (const float*)d_in[2];
    const float* rec_coord = (const float*)d_in[3];
    float* out = (float*)d_out;

    cudaFuncSetAttribute(ff_main_kernel,
                         cudaFuncAttributeMaxDynamicSharedMemorySize,
                         SMEM_BYTES);

    ff_init_kernel<<<1, 32>>>(out);

    // (8, 16, 8) = 1024 CTAs, 1 per SM
    dim3 grid(RDIM / RT, EDIM / ECH, BATCH);
    ff_main_kernel<<<grid, NTHREADS, SMEM_BYTES>>>(lig_feat, rec_feat,
                                                   lig_coord, rec_coord, out);
}

// round 13
// speedup vs baseline: 1.0878x; 1.0878x over previous
#include <cuda_runtime.h>
#include <cstdint>

// Problem constants
#define LDIM   128
#define RDIM   2048
#define EDIM   32
#define FDIM   64
#define KTOT   2048
#define BATCH  8

// Tiling (identical to the 186us R7 kernel): CTA = 128L x 128R x (ECH*64)k,
// 512 threads, thread tile 8L x 4R. Only change: dist -> smem zb table.
#define KT       16
#define RT       128
#define ECH      4
#define NSTAGE   ((ECH*FDIM)/KT)     // 16
#define NTHREADS 512
#define LDSROW   132                 // padded tile row (words)
#define ZROW     132                 // zb padded row (words)

// rbf(d,e) = exp(-((d-mu_e)/sigma)^2) = 2^(-(KC*(d-mu_e))^2)
#define KC_CONST   3.2029930899845557f
#define MU_STEP    (12.0f/31.0f)

// dynamic smem layout (floats)
#define SM_A      0
#define SM_B      (2*KT*LDSROW)                // 4224
#define SM_ZB     (SM_B + 2*KT*LDSROW)         // 8448
#define SM_FLOATS (SM_ZB + LDIM*ZROW)          // 25344
#define SMEM_BYTES (SM_FLOATS*4)               // 101376 B

__device__ __forceinline__ unsigned long long dup2(float x) {
    unsigned long long r;
    unsigned int u = __float_as_uint(x);
    asm("mov.b64 %0, {%1, %1};" : "=l"(r) : "r"(u));
    return r;
}
__device__ __forceinline__ void fma2(unsigned long long &acc,
                                     unsigned long long a,
                                     unsigned long long b) {
    asm("fma.rn.f32x2 %0, %1, %2, %0;" : "+l"(acc) : "l"(a), "l"(b));
}
__device__ __forceinline__ void unpack2(unsigned long long v, float &lo, float &hi) {
    unsigned int a, b;
    asm("mov.b64 {%0, %1}, %2;" : "=r"(a), "=r"(b) : "l"(v));
    lo = __uint_as_float(a);
    hi = __uint_as_float(b);
}
__device__ __forceinline__ float ex2a(float x) {
    float r; asm("ex2.approx.ftz.f32 %0, %1;" : "=f"(r) : "f"(x)); return r;
}
__device__ __forceinline__ float sqrta(float x) {
    float r; asm("sqrt.approx.f32 %0, %1;" : "=f"(r) : "f"(x)); return r;
}

__global__ void ff_init_kernel(float* out) {
    if (threadIdx.x < BATCH) out[threadIdx.x] = 0.0f;
}

__global__ void __launch_bounds__(NTHREADS, 1)
ff_main_kernel(const float* __restrict__ ligf,
               const float* __restrict__ recf,
               const float* __restrict__ ligc,
               const float* __restrict__ recc,
               float* __restrict__ out)
{
    extern __shared__ __align__(16) float smem[];
    float* As = smem + SM_A;
    float* Bs = smem + SM_B;
    float* zb = smem + SM_ZB;

    const int tid  = threadIdx.x;
    const int lane = tid & 31;          // owns r = 4*lane .. 4*lane+3
    const int w    = tid >> 5;          // 0..15; owns l = w*8 .. w*8+7
    const int l0   = w * 8;

    const int rt = blockIdx.x;          // 0..15
    const int ec = blockIdx.y;          // 0..7
    const int b  = blockIdx.z;          // 0..7

    const int r0    = rt * RT;
    const int e0    = ec * ECH;
    const int kbase = e0 * FDIM;

    const float* Ag = ligf + (size_t)b * LDIM * KTOT + kbase;
    const float* Bg = recf + ((size_t)b * RDIM + r0) * KTOT + kbase;

    // staging: each thread one float4 (4 consecutive k) per tile per stage
    const int srow = tid >> 2;          // 0..127
    const int scol = (tid & 3) * 4;     // 0,4,8,12

    // ---- stage coords into smem (tile area, overwritten later) ----
    {
        float* lc = As;                 // [128][3]
        float* rc = As + 512;           // [128][3]
        for (int i = tid; i < LDIM * 3; i += NTHREADS)
            lc[i] = ligc[(size_t)b * LDIM * 3 + i];
        for (int i = tid; i < RT * 3; i += NTHREADS)
            rc[i] = recc[((size_t)b * RDIM + r0) * 3 + i];
        __syncthreads();

        // issue stage-0 LDG early (overlaps the sqrt burst below)
        float4 pa = *(const float4*)(Ag + (size_t)srow * KTOT + scol);
        float4 pb = *(const float4*)(Bg + (size_t)srow * KTOT + scol);

        // zb[l][r] = KC * dist(l, r0+r): 32 entries per thread
        {
            const int l  = tid >> 2;            // 0..127
            const int rq = (tid & 3) * 32;      // r block of 32
            const float lx = lc[l * 3], ly = lc[l * 3 + 1], lz = lc[l * 3 + 2];
            float* zrow = zb + l * ZROW + rq;
            const float* rcp = rc + rq * 3;
            #pragma unroll 4
            for (int i = 0; i < 32; i++) {
                float dx = lx - rcp[i * 3], dy = ly - rcp[i * 3 + 1],
                      dz = lz - rcp[i * 3 + 2];
                float dd = fmaf(dx, dx, fmaf(dy, dy, dz * dz));
                zrow[i] = KC_CONST * sqrta(dd);
            }
        }
        __syncthreads();

        // store stage 0
        float va[4] = {pa.x, pa.y, pa.z, pa.w};
        float vb[4] = {pb.x, pb.y, pb.z, pb.w};
        #pragma unroll
        for (int j = 0; j < 4; j++) {
            As[(scol + j) * LDSROW + srow] = va[j];
            Bs[(scol + j) * LDSROW + srow] = vb[j];
        }
    }

    // acc[p][j] = packed {l = l0+2p, l0+2p+1} x r = 4*lane+j
    unsigned long long acc[4][4];
    #pragma unroll
    for (int p = 0; p < 4; p++)
        #pragma unroll
        for (int j = 0; j < 4; j++)
            acc[p][j] = 0ULL;

    float u_acc = 0.0f;

    // prefetch stage 1
    float4 pa, pb;
    pa = *(const float4*)(Ag + (size_t)srow * KTOT + KT + scol);
    pb = *(const float4*)(Bg + (size_t)srow * KTOT + KT + scol);

    #pragma unroll 1
    for (int s = 0; s < NSTAGE; s++) {
        const int buf = s & 1;
        float* Asb = As + buf * (KT * LDSROW);
        float* Bsb = Bs + buf * (KT * LDSROW);
        __syncthreads();

        // ---- main compute: KT k-steps, 8L x 4R per thread ----
        #pragma unroll
        for (int k = 0; k < KT; k++) {
            unsigned long long a2[4];
            {
                const ulonglong2* Ar =
                    (const ulonglong2*)(Asb + k * LDSROW + l0);
                ulonglong2 t0 = Ar[0];
                ulonglong2 t1 = Ar[1];
                a2[0] = t0.x; a2[1] = t0.y; a2[2] = t1.x; a2[3] = t1.y;
            }
            float4 bf = *(const float4*)(Bsb + k * LDSROW + 4 * lane);
            unsigned long long b2[4];
            b2[0] = dup2(bf.x);
            b2[1] = dup2(bf.y);
            b2[2] = dup2(bf.z);
            b2[3] = dup2(bf.w);

            #pragma unroll
            for (int p = 0; p < 4; p++)
                #pragma unroll
                for (int j = 0; j < 4; j++)
                    fma2(acc[p][j], a2[p], b2[j]);
        }

        // ---- store prefetched next tile; fetch the one after ----
        if (s + 1 < NSTAGE) {
            const int nbuf = (s + 1) & 1;
            float* Asn = As + nbuf * (KT * LDSROW);
            float* Bsn = Bs + nbuf * (KT * LDSROW);
            float va[4] = {pa.x, pa.y, pa.z, pa.w};
            float vb[4] = {pb.x, pb.y, pb.z, pb.w};
            #pragma unroll
            for (int j = 0; j < 4; j++) {
                Asn[(scol + j) * LDSROW + srow] = va[j];
                Bsn[(scol + j) * LDSROW + srow] = vb[j];
            }
            if (s + 2 < NSTAGE) {
                const int ko = (s + 2) * KT + scol;
                pa = *(const float4*)(Ag + (size_t)srow * KTOT + ko);
                pb = *(const float4*)(Bg + (size_t)srow * KTOT + ko);
            }
        }

        // ---- epilogue fold at each e boundary (every 4 stages) ----
        if ((s & 3) == 3) {
            const int e = e0 + (s >> 2);
            const float c2 = KC_CONST * MU_STEP * (float)e;
            #pragma unroll
            for (int p = 0; p < 4; p++) {
                float4 za = *(const float4*)(zb + (l0 + 2 * p) * ZROW + 4 * lane);
                float4 zc = *(const float4*)(zb + (l0 + 2 * p + 1) * ZROW + 4 * lane);
                float z0v[4] = {za.x, za.y, za.z, za.w};
                float z1v[4] = {zc.x, zc.y, zc.z, zc.w};
                #pragma unroll
                for (int j = 0; j < 4; j++) {
                    float dot0, dot1;
                    unpack2(acc[p][j], dot0, dot1);
                    float q0 = z0v[j] - c2;
                    float q1 = z1v[j] - c2;
                    u_acc = fmaf(ex2a(-q0 * q0), dot0, u_acc);
                    u_acc = fmaf(ex2a(-q1 * q1), dot1, u_acc);
                    acc[p][j] = 0ULL;
                }
            }
        }
    }

    // ---- block reduction + atomic accumulate into U[b] ----
    #pragma unroll
    for (int o = 16; o > 0; o >>= 1)
        u_acc += __shfl_xor_sync(0xffffffffu, u_acc, o);

    __syncthreads();
    float* red = smem;
    if (lane == 0) red[w] = u_acc;
    __syncthreads();
    if (tid == 0) {
        float ssum = 0.0f;
        #pragma unroll
        for (int ww = 0; ww < NTHREADS / 32; ww++) ssum += red[ww];
        atomicAdd(out + b, ssum * 0.01f);   // ENERGY_SCALE
    }
}

extern "C" void kernel_launch(void* const* d_in, const int* in_sizes, int n_in,
                              void* d_out, int out_size) {
    (void)in_sizes; (void)n_in; (void)out_size;
    const float* lig_feat  = (const float*)d_in[0];
    const float* rec_feat  = (const float*)d_in[1];
    const float* lig_coord = (const float*)d_in[2];
    const float* rec_coord = (const float*)d_in[3];
    float* out = (float*)d_out;

    cudaFuncSetAttribute(ff_main_kernel,
                         cudaFuncAttributeMaxDynamicSharedMemorySize,
                         SMEM_BYTES);

    ff_init_kernel<<<1, 32>>>(out);

    // (16, 8, 8) = 1024 CTAs, 1 per SM
    dim3 grid(RDIM / RT, EDIM / ECH, BATCH);
    ff_main_kernel<<<grid, NTHREADS, SMEM_BYTES>>>(lig_feat, rec_feat,
                                                   lig_coord, rec_coord, out);
}